// round 1
// baseline (speedup 1.0000x reference)
#include <cuda_runtime.h>
#include <cuda_bf16.h>
#include <cstdint>
#include <cstddef>

// Problem constants
#define BB 256
#define SS 256
#define EE 384
#define HH 6
#define DH 64
#define FF 1536
#define MM (BB*SS)          // 65536
#define NQKV (3*HH*DH)      // 1152
#define BHSD ((size_t)BB*HH*SS*DH)  // 25,165,824

// ---------------- scratch (device globals; no allocation allowed) ----------
__device__ float g_hln[(size_t)MM*EE];
__device__ float g_qkv[3*BHSD];
__device__ float g_o[(size_t)MM*EE];
__device__ float g_x1[(size_t)MM*EE];
__device__ float g_h2[(size_t)MM*EE];
__device__ float g_mid[(size_t)MM*FF];
__device__ float g_Wqkv[(size_t)EE*NQKV];

// ---------------- pack Wq/Wk/Wv into [E x 1152] row-major B matrix ---------
__global__ void pack_w_kernel(const float* __restrict__ Wq,
                              const float* __restrict__ Wk,
                              const float* __restrict__ Wv) {
    int idx = blockIdx.x * blockDim.x + threadIdx.x;
    if (idx >= EE * NQKV) return;
    int e = idx / NQKV;
    int j = idx - e * NQKV;
    int m = j / (HH * DH);
    int jj = j - m * (HH * DH);
    int h = jj >> 6;
    int d = jj & 63;
    const float* W = (m == 0) ? Wq : (m == 1) ? Wk : Wv;
    g_Wqkv[idx] = W[((size_t)h * EE + e) * DH + d];
}

// ---------------- LayerNorm: one block (128 thr) per row of 384 ------------
__global__ void ln_kernel(const float* __restrict__ in,
                          const float* __restrict__ gamma,
                          const float* __restrict__ beta,
                          float* __restrict__ out) {
    __shared__ float red1[4];
    __shared__ float red2[4];
    int row = blockIdx.x;
    int tid = threadIdx.x;
    const float* r = in + (size_t)row * EE;
    float v0 = r[tid], v1 = r[tid + 128], v2 = r[tid + 256];
    float s = v0 + v1 + v2;
    #pragma unroll
    for (int o = 16; o; o >>= 1) s += __shfl_xor_sync(0xffffffffu, s, o);
    if ((tid & 31) == 0) red1[tid >> 5] = s;
    __syncthreads();
    float mu = (red1[0] + red1[1] + red1[2] + red1[3]) * (1.0f / 384.0f);
    float d0 = v0 - mu, d1 = v1 - mu, d2 = v2 - mu;
    float vs = d0 * d0 + d1 * d1 + d2 * d2;
    #pragma unroll
    for (int o = 16; o; o >>= 1) vs += __shfl_xor_sync(0xffffffffu, vs, o);
    if ((tid & 31) == 0) red2[tid >> 5] = vs;
    __syncthreads();
    float var = (red2[0] + red2[1] + red2[2] + red2[3]) * (1.0f / 384.0f);
    float rstd = rsqrtf(var + 1e-5f);
    float* w = out + (size_t)row * EE;
    w[tid]       = d0 * rstd * gamma[tid]       + beta[tid];
    w[tid + 128] = d1 * rstd * gamma[tid + 128] + beta[tid + 128];
    w[tid + 256] = d2 * rstd * gamma[tid + 256] + beta[tid + 256];
}

// ---------------- generic SGEMM 128x128x8, 256 threads, 8x8 microtile ------
// mode 0: QKV scatter (C points at g_qkv base), no bias/resid
// mode 1: C = resid + acc + bias
// mode 2: C = relu(acc + bias)
#define BM 128
#define BN 128
#define BK 8

__global__ __launch_bounds__(256, 2)
void sgemm_kernel(const float* __restrict__ A, const float* __restrict__ B,
                  float* __restrict__ C, int M, int N, int K,
                  int mode, const float* __restrict__ bias,
                  const float* __restrict__ resid) {
    __shared__ float As[BK][BM + 4];
    __shared__ float Bs[BK][BN];
    int bx = blockIdx.x;   // N tile
    int by = blockIdx.y;   // M tile
    int tid = threadIdx.x;
    int tx = tid & 15;
    int ty = tid >> 4;

    int arow = tid >> 1;
    int acol = (tid & 1) << 2;
    int brow = tid >> 5;
    int bcol = (tid & 31) << 2;

    const float* Ab = A + (size_t)(by * BM) * K;
    const float* Bb = B + bx * BN;

    float acc[8][8];
    #pragma unroll
    for (int i = 0; i < 8; i++)
        #pragma unroll
        for (int j = 0; j < 8; j++) acc[i][j] = 0.0f;

    for (int k0 = 0; k0 < K; k0 += BK) {
        float4 a4 = *(const float4*)(Ab + (size_t)arow * K + k0 + acol);
        As[acol + 0][arow] = a4.x;
        As[acol + 1][arow] = a4.y;
        As[acol + 2][arow] = a4.z;
        As[acol + 3][arow] = a4.w;
        float4 b4 = *(const float4*)(Bb + (size_t)(k0 + brow) * N + bcol);
        *(float4*)&Bs[brow][bcol] = b4;
        __syncthreads();
        #pragma unroll
        for (int k = 0; k < BK; k++) {
            float ra[8], rb[8];
            *(float4*)&ra[0] = *(const float4*)&As[k][ty * 4];
            *(float4*)&ra[4] = *(const float4*)&As[k][ty * 4 + 64];
            *(float4*)&rb[0] = *(const float4*)&Bs[k][tx * 4];
            *(float4*)&rb[4] = *(const float4*)&Bs[k][tx * 4 + 64];
            #pragma unroll
            for (int i = 0; i < 8; i++)
                #pragma unroll
                for (int j = 0; j < 8; j++)
                    acc[i][j] = fmaf(ra[i], rb[j], acc[i][j]);
        }
        __syncthreads();
    }

    int row_base = by * BM;
    int col_base = bx * BN;
    #pragma unroll
    for (int i = 0; i < 8; i++) {
        int r = row_base + (ty << 2) + (i & 3) + ((i >> 2) << 6);
        #pragma unroll
        for (int jg = 0; jg < 2; jg++) {
            int c = col_base + (tx << 2) + (jg << 6);
            float v[4];
            #pragma unroll
            for (int jj = 0; jj < 4; jj++) v[jj] = acc[i][jg * 4 + jj];
            if (mode == 0) {
                // scatter into g_qkv: col -> (m, h, d); row -> (b, s)
                int b = r >> 8;
                int s = r & 255;
                #pragma unroll
                for (int jj = 0; jj < 4; jj++) {
                    int col = c + jj;
                    int m = col / (HH * DH);
                    int rem = col - m * (HH * DH);
                    int h = rem >> 6;
                    int d = rem & 63;
                    C[(size_t)m * BHSD + (((size_t)(b * HH + h) * SS + s) * DH) + d] = v[jj];
                }
            } else {
                #pragma unroll
                for (int jj = 0; jj < 4; jj++) v[jj] += bias[c + jj];
                if (mode == 2) {
                    #pragma unroll
                    for (int jj = 0; jj < 4; jj++) v[jj] = fmaxf(v[jj], 0.0f);
                } else {
                    float4 rr = *(const float4*)(resid + (size_t)r * N + c);
                    v[0] += rr.x; v[1] += rr.y; v[2] += rr.z; v[3] += rr.w;
                }
                float4 o4 = make_float4(v[0], v[1], v[2], v[3]);
                *(float4*)(C + (size_t)r * N + c) = o4;
            }
        }
    }
}

// ---------------- attention: one block per (b,h), one thread per query row --
// K,V resident in 128KB dynamic smem; two-pass softmax (max pass, then
// exp/sum/AV with dot recompute). Causal handled by t<=s loop bound.
__global__ __launch_bounds__(256, 1)
void attn_kernel(float* __restrict__ o_out) {
    extern __shared__ float sm[];
    float* Ksm = sm;               // S*DH
    float* Vsm = sm + SS * DH;     // S*DH
    int bh = blockIdx.x;
    int b = bh / HH;
    int h = bh - b * HH;
    int tid = threadIdx.x;

    const float* qb = g_qkv + (size_t)bh * SS * DH;
    const float* kb = g_qkv + BHSD + (size_t)bh * SS * DH;
    const float* vb = g_qkv + 2 * BHSD + (size_t)bh * SS * DH;

    const float4* k4 = (const float4*)kb;
    const float4* v4 = (const float4*)vb;
    float4* Ks4 = (float4*)Ksm;
    float4* Vs4 = (float4*)Vsm;
    #pragma unroll
    for (int i = 0; i < (SS * DH / 4) / 256; i++) {
        int idx = tid + i * 256;
        Ks4[idx] = k4[idx];
        Vs4[idx] = v4[idx];
    }
    __syncthreads();

    int s = tid;
    float4 q[16];
    const float4* qr = (const float4*)(qb + (size_t)s * DH);
    #pragma unroll
    for (int i = 0; i < 16; i++) q[i] = qr[i];

    const float scale = 0.125f;  // 1/sqrt(64)

    // pass 1: row max
    float mx = -1e30f;
    for (int t = 0; t <= s; t++) {
        const float4* kr = (const float4*)(Ksm + t * DH);
        float acc = 0.0f;
        #pragma unroll
        for (int i = 0; i < 16; i++) {
            float4 kk = kr[i];
            acc = fmaf(q[i].x, kk.x, acc);
            acc = fmaf(q[i].y, kk.y, acc);
            acc = fmaf(q[i].z, kk.z, acc);
            acc = fmaf(q[i].w, kk.w, acc);
        }
        mx = fmaxf(mx, acc * scale);
    }

    // pass 2: exp, sum, AV
    float sum = 0.0f;
    float4 o[16];
    #pragma unroll
    for (int i = 0; i < 16; i++) o[i] = make_float4(0.f, 0.f, 0.f, 0.f);
    for (int t = 0; t <= s; t++) {
        const float4* kr = (const float4*)(Ksm + t * DH);
        float acc = 0.0f;
        #pragma unroll
        for (int i = 0; i < 16; i++) {
            float4 kk = kr[i];
            acc = fmaf(q[i].x, kk.x, acc);
            acc = fmaf(q[i].y, kk.y, acc);
            acc = fmaf(q[i].z, kk.z, acc);
            acc = fmaf(q[i].w, kk.w, acc);
        }
        float p = __expf(acc * scale - mx);
        sum += p;
        const float4* vr = (const float4*)(Vsm + t * DH);
        #pragma unroll
        for (int i = 0; i < 16; i++) {
            float4 vv = vr[i];
            o[i].x = fmaf(p, vv.x, o[i].x);
            o[i].y = fmaf(p, vv.y, o[i].y);
            o[i].z = fmaf(p, vv.z, o[i].z);
            o[i].w = fmaf(p, vv.w, o[i].w);
        }
    }
    float inv = 1.0f / sum;
    float4* ow = (float4*)(o_out + ((size_t)(b * SS + s)) * EE + h * DH);
    #pragma unroll
    for (int i = 0; i < 16; i++) {
        ow[i] = make_float4(o[i].x * inv, o[i].y * inv, o[i].z * inv, o[i].w * inv);
    }
}

// ---------------- launch ---------------------------------------------------
extern "C" void kernel_launch(void* const* d_in, const int* in_sizes, int n_in,
                              void* d_out, int out_size) {
    const float* x   = (const float*)d_in[0];
    const float* Wq  = (const float*)d_in[1];
    const float* Wk  = (const float*)d_in[2];
    const float* Wv  = (const float*)d_in[3];
    const float* Wp  = (const float*)d_in[4];
    const float* bp  = (const float*)d_in[5];
    const float* W1  = (const float*)d_in[6];
    const float* b1  = (const float*)d_in[7];
    const float* W2  = (const float*)d_in[8];
    const float* b2  = (const float*)d_in[9];
    const float* g1  = (const float*)d_in[10];
    const float* be1 = (const float*)d_in[11];
    const float* g2  = (const float*)d_in[12];
    const float* be2 = (const float*)d_in[13];
    float* out = (float*)d_out;

    float *hln, *qkv, *o, *x1, *h2, *mid, *wqkv;
    cudaGetSymbolAddress((void**)&hln,  g_hln);
    cudaGetSymbolAddress((void**)&qkv,  g_qkv);
    cudaGetSymbolAddress((void**)&o,    g_o);
    cudaGetSymbolAddress((void**)&x1,   g_x1);
    cudaGetSymbolAddress((void**)&h2,   g_h2);
    cudaGetSymbolAddress((void**)&mid,  g_mid);
    cudaGetSymbolAddress((void**)&wqkv, g_Wqkv);

    cudaFuncSetAttribute(attn_kernel,
                         cudaFuncAttributeMaxDynamicSharedMemorySize,
                         2 * SS * DH * (int)sizeof(float));

    // 1. pack QKV weight matrix [E x 1152]
    pack_w_kernel<<<(EE * NQKV + 255) / 256, 256>>>(Wq, Wk, Wv);
    // 2. LN1
    ln_kernel<<<MM, 128>>>(x, g1, be1, hln);
    // 3. QKV projection (scatter epilogue)
    sgemm_kernel<<<dim3(NQKV / BN, MM / BM), 256>>>(
        hln, wqkv, qkv, MM, NQKV, EE, 0, nullptr, nullptr);
    // 4. causal attention -> o in [b, s, (h,d)] layout
    attn_kernel<<<BB * HH, 256, 2 * SS * DH * sizeof(float)>>>(o);
    // 5. output projection + residual: x1 = x + o@Wp + bp
    sgemm_kernel<<<dim3(EE / BN, MM / BM), 256>>>(
        o, Wp, x1, MM, EE, EE, 1, bp, x);
    // 6. LN2
    ln_kernel<<<MM, 128>>>(x1, g2, be2, h2);
    // 7. FFN1: mid = relu(h2@W1 + b1)
    sgemm_kernel<<<dim3(FF / BN, MM / BM), 256>>>(
        h2, W1, mid, MM, FF, EE, 2, b1, nullptr);
    // 8. FFN2: out = x1 + mid@W2 + b2
    sgemm_kernel<<<dim3(EE / BN, MM / BM), 256>>>(
        mid, W2, out, MM, EE, FF, 1, b2, x1);
}

// round 5
// speedup vs baseline: 1.3209x; 1.3209x over previous
#include <cuda_runtime.h>
#include <cuda_bf16.h>
#include <cstdint>
#include <cstddef>

// ---------------- problem constants ----------------------------------------
#define BB 256
#define SS 256
#define EE 384
#define HH 6
#define DH 64
#define FF 1536
#define MM (BB*SS)                  // 65536
#define BHSD ((size_t)BB*HH*SS*DH)  // 25,165,824

// ---------------- scratch (device globals; no allocation allowed) ----------
__device__ __nv_bfloat16 g_hln[2ull*MM*EE];   // LN1 out hi/lo planes
__device__ float         g_qkv[3*BHSD];       // q,k,v fp32 [3][B,H,S,D]
__device__ __nv_bfloat16 g_o[2ull*MM*EE];     // attention out hi/lo
__device__ float         g_x1[(size_t)MM*EE]; // x + proj (fp32)
__device__ __nv_bfloat16 g_h2[2ull*MM*EE];    // LN2 out hi/lo
__device__ __nv_bfloat16 g_mid[2ull*MM*FF];   // relu(ffn1) hi/lo
__device__ __nv_bfloat16 g_wqkv[2ull*1152*384];
__device__ __nv_bfloat16 g_wp[2ull*384*384];
__device__ __nv_bfloat16 g_w1[2ull*1536*384];
__device__ __nv_bfloat16 g_w2[2ull*384*1536];

// ---------------- helpers ---------------------------------------------------
__device__ __forceinline__ uint32_t smem_to_u32(const void* p) {
    uint32_t a;
    asm("{ .reg .u64 t; cvta.to.shared.u64 t, %1; cvt.u32.u64 %0, t; }"
        : "=r"(a) : "l"(p));
    return a;
}

#define CP_ASYNC16(sm, gp) \
    asm volatile("cp.async.cg.shared.global [%0], [%1], 16;" \
        :: "r"((uint32_t)(sm)), "l"(gp) : "memory")
#define CP_COMMIT() asm volatile("cp.async.commit_group;" ::: "memory")
#define CP_WAIT2()  asm volatile("cp.async.wait_group 2;" ::: "memory")

__device__ __forceinline__ void ldsm_x4(uint32_t* r, uint32_t addr) {
    asm volatile("ldmatrix.sync.aligned.m8n8.x4.shared.b16 {%0,%1,%2,%3}, [%4];"
        : "=r"(r[0]), "=r"(r[1]), "=r"(r[2]), "=r"(r[3]) : "r"(addr));
}
__device__ __forceinline__ void ldsm_x2(uint32_t* r, uint32_t addr) {
    asm volatile("ldmatrix.sync.aligned.m8n8.x2.shared.b16 {%0,%1}, [%2];"
        : "=r"(r[0]), "=r"(r[1]) : "r"(addr));
}
__device__ __forceinline__ void mma16816(float* d, const uint32_t* a, const uint32_t* b) {
    asm volatile(
        "mma.sync.aligned.m16n8k16.row.col.f32.bf16.bf16.f32 "
        "{%0,%1,%2,%3}, {%4,%5,%6,%7}, {%8,%9}, {%0,%1,%2,%3};"
        : "+f"(d[0]), "+f"(d[1]), "+f"(d[2]), "+f"(d[3])
        : "r"(a[0]), "r"(a[1]), "r"(a[2]), "r"(a[3]), "r"(b[0]), "r"(b[1]));
}

__device__ __forceinline__ void split_bf16(float v, __nv_bfloat16& hi, __nv_bfloat16& lo) {
    hi = __float2bfloat16(v);
    lo = __float2bfloat16(v - __bfloat162float(hi));
}

// ---------------- weight packing -------------------------------------------
__global__ void pack_qkv_kernel(const float* __restrict__ Wq,
                                const float* __restrict__ Wk,
                                const float* __restrict__ Wv) {
    int idx = blockIdx.x * 256 + threadIdx.x;
    if (idx >= 1152 * 384) return;
    int n = idx / 384, k = idx - n * 384;
    int m3 = n / 384;
    int rem = n - m3 * 384;
    int h = rem >> 6, d = rem & 63;
    const float* W = (m3 == 0) ? Wq : (m3 == 1) ? Wk : Wv;
    float v = W[((size_t)h * 384 + k) * 64 + d];
    __nv_bfloat16 hi, lo; split_bf16(v, hi, lo);
    g_wqkv[idx] = hi;
    g_wqkv[1152 * 384 + idx] = lo;
}

// B[n,k] = src[k*ldn + n], planes [2][N][K]
__global__ void pack_gen_kernel(const float* __restrict__ src, __nv_bfloat16* dst,
                                int N, int K, int ldn) {
    int idx = blockIdx.x * 256 + threadIdx.x;
    if (idx >= N * K) return;
    int n = idx / K, k = idx - n * K;
    float v = src[(size_t)k * ldn + n];
    __nv_bfloat16 hi, lo; split_bf16(v, hi, lo);
    dst[idx] = hi;
    dst[(size_t)N * K + idx] = lo;
}

// ---------------- LayerNorm -> hi/lo bf16 planes ---------------------------
__global__ void ln_kernel(const float* __restrict__ in,
                          const float* __restrict__ gamma,
                          const float* __restrict__ beta,
                          __nv_bfloat16* __restrict__ out) {
    __shared__ float red1[4];
    __shared__ float red2[4];
    int row = blockIdx.x;
    int tid = threadIdx.x;
    const float* r = in + (size_t)row * EE;
    float v0 = r[tid], v1 = r[tid + 128], v2 = r[tid + 256];
    float s = v0 + v1 + v2;
    #pragma unroll
    for (int o = 16; o; o >>= 1) s += __shfl_xor_sync(0xffffffffu, s, o);
    if ((tid & 31) == 0) red1[tid >> 5] = s;
    __syncthreads();
    float mu = (red1[0] + red1[1] + red1[2] + red1[3]) * (1.0f / 384.0f);
    float d0 = v0 - mu, d1 = v1 - mu, d2 = v2 - mu;
    float vs = d0 * d0 + d1 * d1 + d2 * d2;
    #pragma unroll
    for (int o = 16; o; o >>= 1) vs += __shfl_xor_sync(0xffffffffu, vs, o);
    if ((tid & 31) == 0) red2[tid >> 5] = vs;
    __syncthreads();
    float var = (red2[0] + red2[1] + red2[2] + red2[3]) * (1.0f / 384.0f);
    float rstd = rsqrtf(var + 1e-5f);
    __nv_bfloat16* hip = out + (size_t)row * EE;
    __nv_bfloat16* lop = hip + (size_t)MM * EE;
    #pragma unroll
    for (int j = 0; j < 3; j++) {
        int c = tid + j * 128;
        float d = (j == 0) ? d0 : (j == 1) ? d1 : d2;
        float y = d * rstd * gamma[c] + beta[c];
        __nv_bfloat16 hi, lo; split_bf16(y, hi, lo);
        hip[c] = hi;
        lop[c] = lo;
    }
}

// ---------------- mma.sync GEMM --------------------------------------------
// D[M,N] = sum over 3 segments: A_seg[M,K] . B_seg[N,K]^T  (bf16 hi/lo planes)
// seg 0: Ah.Bh   seg 1: Al.Bh   seg 2: Ah.Bl
// modes: 0 = QKV scatter fp32; 1 = resid + D + bias (fp32);
//        2 = relu(D+bias) -> hi/lo bf16; 3 = same as 1
// Tile: 128x128, BK=32, 4-stage cp.async pipeline, 8 warps, warp tile 64x32.
#define STAGE_BYTES 20480   // A: 128*80, B: 128*80
#define GSMEM (4 * STAGE_BYTES)

__global__ __launch_bounds__(256, 1)
void mma_gemm(const __nv_bfloat16* __restrict__ Ah, const __nv_bfloat16* __restrict__ Al,
              const __nv_bfloat16* __restrict__ Bh, const __nv_bfloat16* __restrict__ Bl,
              void* outp, const float* __restrict__ bias,
              const float* __restrict__ resid, int K, int N, int mode) {
    extern __shared__ __align__(128) uint8_t dsm[];
    const uint32_t sb = smem_to_u32(dsm);
    const int tid = threadIdx.x;
    const int lane = tid & 31;
    const int wid = tid >> 5;
    const int wm = wid >> 2;        // 0..1
    const int wn = wid & 3;         // 0..3
    const int m0 = blockIdx.y * 128;
    const int n0 = blockIdx.x * 128;
    const int kch = K >> 5;         // chunks per segment
    const int CT = 3 * kch;

    // per-thread load coordinates (2 chunks of 16B per matrix per stage)
    const int c0 = tid, c1 = tid + 256;
    const int r0 = c0 >> 2, q0 = c0 & 3;
    const int r1 = c1 >> 2, q1 = c1 & 3;

    float acc[4][4][4];
    #pragma unroll
    for (int i = 0; i < 4; i++)
        #pragma unroll
        for (int j = 0; j < 4; j++)
            #pragma unroll
            for (int t = 0; t < 4; t++) acc[i][j][t] = 0.0f;

    // ---- pipeline ----
    #define LOAD_STAGE(c) do { \
        int s_ = (c) & 3; \
        int seg_ = (c) / kch; \
        int kk_ = (c) - seg_ * kch; \
        const __nv_bfloat16* As_ = (seg_ == 1) ? Al : Ah; \
        const __nv_bfloat16* Bs_ = (seg_ == 2) ? Bl : Bh; \
        int k0_ = kk_ << 5; \
        uint32_t sa = sb + s_ * STAGE_BYTES; \
        uint32_t sbm = sa + 10240; \
        CP_ASYNC16(sa  + r0 * 80 + q0 * 16, As_ + (size_t)(m0 + r0) * K + k0_ + q0 * 8); \
        CP_ASYNC16(sa  + r1 * 80 + q1 * 16, As_ + (size_t)(m0 + r1) * K + k0_ + q1 * 8); \
        CP_ASYNC16(sbm + r0 * 80 + q0 * 16, Bs_ + (size_t)(n0 + r0) * K + k0_ + q0 * 8); \
        CP_ASYNC16(sbm + r1 * 80 + q1 * 16, Bs_ + (size_t)(n0 + r1) * K + k0_ + q1 * 8); \
    } while (0)

    LOAD_STAGE(0); CP_COMMIT();
    LOAD_STAGE(1); CP_COMMIT();
    LOAD_STAGE(2); CP_COMMIT();

    const uint32_t a_row = (uint32_t)(wm * 64 + (lane & 15));
    const uint32_t a_coff = (uint32_t)((lane >> 4) * 8) * 2;
    const uint32_t b_row = (uint32_t)(wn * 32 + (lane & 7));
    const uint32_t b_coff = (uint32_t)(((lane >> 3) & 1) * 8) * 2;

    for (int c = 0; c < CT; ++c) {
        CP_WAIT2();
        __syncthreads();
        if (c + 3 < CT) { LOAD_STAGE(c + 3); }
        CP_COMMIT();
        uint32_t sa = sb + (c & 3) * STAGE_BYTES;
        uint32_t sbm = sa + 10240;
        #pragma unroll
        for (int ks = 0; ks < 2; ++ks) {
            uint32_t afr[4][4], bfr[4][2];
            #pragma unroll
            for (int mt = 0; mt < 4; ++mt)
                ldsm_x4(afr[mt], sa + (a_row + mt * 16) * 80 + ks * 32 + a_coff);
            #pragma unroll
            for (int nt = 0; nt < 4; ++nt)
                ldsm_x2(bfr[nt], sbm + (b_row + nt * 8) * 80 + ks * 32 + b_coff);
            #pragma unroll
            for (int mt = 0; mt < 4; ++mt)
                #pragma unroll
                for (int nt = 0; nt < 4; ++nt)
                    mma16816(acc[mt][nt], afr[mt], bfr[nt]);
        }
        __syncthreads();
    }

    // ---- epilogue: direct stores ----
    #pragma unroll
    for (int mt = 0; mt < 4; ++mt) {
        #pragma unroll
        for (int nt = 0; nt < 4; ++nt) {
            int col = n0 + wn * 32 + nt * 8 + (lane & 3) * 2;
            #pragma unroll
            for (int half = 0; half < 2; ++half) {
                int rg = m0 + wm * 64 + mt * 16 + (lane >> 2) + half * 8;
                float v0 = acc[mt][nt][half * 2 + 0];
                float v1 = acc[mt][nt][half * 2 + 1];
                if (mode == 0) {
                    int m3 = col / 384;
                    int rem = col - m3 * 384;
                    int h = rem >> 6, dd = rem & 63;
                    int b = rg >> 8, sq = rg & 255;
                    float2 val = make_float2(v0, v1);
                    *(float2*)((float*)outp + (size_t)m3 * BHSD +
                               ((size_t)((b * HH + h) * SS + sq)) * DH + dd) = val;
                } else if (mode == 2) {
                    float s0 = fmaxf(v0 + bias[col], 0.f);
                    float s1 = fmaxf(v1 + bias[col + 1], 0.f);
                    __nv_bfloat16 h0, l0, h1, l1;
                    split_bf16(s0, h0, l0); split_bf16(s1, h1, l1);
                    __nv_bfloat16* hip = (__nv_bfloat16*)outp;
                    __nv_bfloat16* lop = hip + (size_t)MM * FF;
                    size_t base = (size_t)rg * FF + col;
                    __nv_bfloat162 ph; ph.x = h0; ph.y = h1;
                    __nv_bfloat162 pl; pl.x = l0; pl.y = l1;
                    *(__nv_bfloat162*)(hip + base) = ph;
                    *(__nv_bfloat162*)(lop + base) = pl;
                } else {
                    float2 rr = *(const float2*)(resid + (size_t)rg * N + col);
                    float2 val = make_float2(v0 + bias[col] + rr.x,
                                             v1 + bias[col + 1] + rr.y);
                    *(float2*)((float*)outp + (size_t)rg * N + col) = val;
                }
            }
        }
    }
}

// ---------------- attention: online softmax, bf16 hi/lo output -------------
__global__ __launch_bounds__(256, 1)
void attn_kernel() {
    extern __shared__ float attnsm[];
    float* Ksm = attnsm;
    float* Vsm = attnsm + SS * DH;
    int bh = blockIdx.x;
    int b = bh / HH;
    int h = bh - b * HH;
    int tid = threadIdx.x;

    const float* qb = g_qkv + (size_t)bh * SS * DH;
    const float* kb = g_qkv + BHSD + (size_t)bh * SS * DH;
    const float* vb = g_qkv + 2 * BHSD + (size_t)bh * SS * DH;

    const float4* k4 = (const float4*)kb;
    const float4* v4 = (const float4*)vb;
    float4* Ks4 = (float4*)Ksm;
    float4* Vs4 = (float4*)Vsm;
    #pragma unroll
    for (int i = 0; i < (SS * DH / 4) / 256; i++) {
        int idx = tid + i * 256;
        Ks4[idx] = k4[idx];
        Vs4[idx] = v4[idx];
    }
    __syncthreads();

    int s = tid;
    float4 q[16];
    const float4* qr = (const float4*)(qb + (size_t)s * DH);
    #pragma unroll
    for (int i = 0; i < 16; i++) q[i] = qr[i];

    const float scale = 0.125f;
    float mx = -1e30f, sum = 0.0f;
    float4 o[16];
    #pragma unroll
    for (int i = 0; i < 16; i++) o[i] = make_float4(0.f, 0.f, 0.f, 0.f);

    for (int t = 0; t <= s; t++) {
        const float4* kr = (const float4*)(Ksm + t * DH);
        float acc = 0.0f;
        #pragma unroll
        for (int i = 0; i < 16; i++) {
            float4 kk = kr[i];
            acc = fmaf(q[i].x, kk.x, acc);
            acc = fmaf(q[i].y, kk.y, acc);
            acc = fmaf(q[i].z, kk.z, acc);
            acc = fmaf(q[i].w, kk.w, acc);
        }
        float sc = acc * scale;
        float p;
        if (sc > mx) {
            float corr = __expf(mx - sc);
            sum *= corr;
            #pragma unroll
            for (int i = 0; i < 16; i++) {
                o[i].x *= corr; o[i].y *= corr; o[i].z *= corr; o[i].w *= corr;
            }
            mx = sc;
            p = 1.0f;
        } else {
            p = __expf(sc - mx);
        }
        sum += p;
        const float4* vr = (const float4*)(Vsm + t * DH);
        #pragma unroll
        for (int i = 0; i < 16; i++) {
            float4 vv = vr[i];
            o[i].x = fmaf(p, vv.x, o[i].x);
            o[i].y = fmaf(p, vv.y, o[i].y);
            o[i].z = fmaf(p, vv.z, o[i].z);
            o[i].w = fmaf(p, vv.w, o[i].w);
        }
    }
    float inv = 1.0f / sum;
    size_t off = (size_t)(b * SS + s) * EE + h * DH;
    __nv_bfloat16* hip = g_o + off;
    __nv_bfloat16* lop = g_o + (size_t)MM * EE + off;
    #pragma unroll
    for (int i = 0; i < 16; i++) {
        float f[4] = { o[i].x * inv, o[i].y * inv, o[i].z * inv, o[i].w * inv };
        __nv_bfloat162 ph, pl;
        __nv_bfloat16 hi, lo;
        split_bf16(f[0], hi, lo); ph.x = hi; pl.x = lo;
        split_bf16(f[1], hi, lo); ph.y = hi; pl.y = lo;
        *(__nv_bfloat162*)(hip + i * 4) = ph;
        *(__nv_bfloat162*)(lop + i * 4) = pl;
        split_bf16(f[2], hi, lo); ph.x = hi; pl.x = lo;
        split_bf16(f[3], hi, lo); ph.y = hi; pl.y = lo;
        *(__nv_bfloat162*)(hip + i * 4 + 2) = ph;
        *(__nv_bfloat162*)(lop + i * 4 + 2) = pl;
    }
}

// ---------------- host -----------------------------------------------------
extern "C" void kernel_launch(void* const* d_in, const int* in_sizes, int n_in,
                              void* d_out, int out_size) {
    const float* x   = (const float*)d_in[0];
    const float* Wq  = (const float*)d_in[1];
    const float* Wk  = (const float*)d_in[2];
    const float* Wv  = (const float*)d_in[3];
    const float* Wp  = (const float*)d_in[4];
    const float* bp  = (const float*)d_in[5];
    const float* W1  = (const float*)d_in[6];
    const float* b1  = (const float*)d_in[7];
    const float* W2  = (const float*)d_in[8];
    const float* b2  = (const float*)d_in[9];
    const float* g1  = (const float*)d_in[10];
    const float* be1 = (const float*)d_in[11];
    const float* g2  = (const float*)d_in[12];
    const float* be2 = (const float*)d_in[13];
    float* out = (float*)d_out;

    void *hlnv, *qkvv, *ov, *x1v, *h2v, *midv, *wqkvv, *wpv, *w1v, *w2v;
    cudaGetSymbolAddress(&hlnv,  g_hln);
    cudaGetSymbolAddress(&qkvv,  g_qkv);
    cudaGetSymbolAddress(&ov,    g_o);
    cudaGetSymbolAddress(&x1v,   g_x1);
    cudaGetSymbolAddress(&h2v,   g_h2);
    cudaGetSymbolAddress(&midv,  g_mid);
    cudaGetSymbolAddress(&wqkvv, g_wqkv);
    cudaGetSymbolAddress(&wpv,   g_wp);
    cudaGetSymbolAddress(&w1v,   g_w1);
    cudaGetSymbolAddress(&w2v,   g_w2);

    __nv_bfloat16* hln  = (__nv_bfloat16*)hlnv;
    float*         qkv  = (float*)qkvv;
    __nv_bfloat16* o    = (__nv_bfloat16*)ov;
    float*         x1   = (float*)x1v;
    __nv_bfloat16* h2   = (__nv_bfloat16*)h2v;
    __nv_bfloat16* mid  = (__nv_bfloat16*)midv;
    __nv_bfloat16* wqkv = (__nv_bfloat16*)wqkvv;
    __nv_bfloat16* wp   = (__nv_bfloat16*)wpv;
    __nv_bfloat16* w1   = (__nv_bfloat16*)w1v;
    __nv_bfloat16* w2   = (__nv_bfloat16*)w2v;

    cudaFuncSetAttribute(mma_gemm, cudaFuncAttributeMaxDynamicSharedMemorySize, GSMEM);
    cudaFuncSetAttribute(attn_kernel, cudaFuncAttributeMaxDynamicSharedMemorySize,
                         2 * SS * DH * (int)sizeof(float));

    // weight packing (hi/lo bf16)
    pack_qkv_kernel<<<(1152 * 384 + 255) / 256, 256>>>(Wq, Wk, Wv);
    pack_gen_kernel<<<(384 * 384 + 255) / 256, 256>>>(Wp, wp, 384, 384, 384);
    pack_gen_kernel<<<(1536 * 384 + 255) / 256, 256>>>(W1, w1, 1536, 384, 1536);
    pack_gen_kernel<<<(384 * 1536 + 255) / 256, 256>>>(W2, w2, 384, 1536, 384);
    // LN1
    ln_kernel<<<MM, 128>>>(x, g1, be1, hln);
    // QKV projection (scatter into [3][B,H,S,D] fp32)
    mma_gemm<<<dim3(9, 512), 256, GSMEM>>>(
        hln, hln + (size_t)MM * EE, wqkv, wqkv + (size_t)1152 * 384,
        qkv, nullptr, nullptr, 384, 1152, 0);
    // causal attention
    attn_kernel<<<BB * HH, 256, 2 * SS * DH * sizeof(float)>>>();
    // out projection + residual: x1 = x + o@Wp + bp
    mma_gemm<<<dim3(3, 512), 256, GSMEM>>>(
        o, o + (size_t)MM * EE, wp, wp + (size_t)384 * 384,
        x1, bp, x, 384, 384, 1);
    // LN2
    ln_kernel<<<MM, 128>>>(x1, g2, be2, h2);
    // FFN1 + relu -> hi/lo bf16
    mma_gemm<<<dim3(12, 512), 256, GSMEM>>>(
        h2, h2 + (size_t)MM * EE, w1, w1 + (size_t)1536 * 384,
        mid, b1, nullptr, 384, 1536, 2);
    // FFN2 + residual -> out
    mma_gemm<<<dim3(3, 512), 256, GSMEM>>>(
        mid, mid + (size_t)MM * FF, w2, w2 + (size_t)384 * 1536,
        out, b2, x1, 1536, 384, 3);
}

// round 7
// speedup vs baseline: 1.7464x; 1.3221x over previous
#include <cuda_runtime.h>
#include <cuda_bf16.h>
#include <cstdint>
#include <cstddef>

// ---------------- problem constants ----------------------------------------
#define BB 256
#define SS 256
#define EE 384
#define HH 6
#define DH 64
#define FF 1536
#define MM (BB*SS)                  // 65536
#define BHSD ((size_t)BB*HH*SS*DH)  // 25,165,824

// ---------------- scratch (device globals; no allocation allowed) ----------
__device__ __nv_bfloat16 g_hln[2ull*MM*EE];   // LN1 out hi/lo planes
__device__ float         g_qkv[3*BHSD];       // q,k,v fp32 [3][B,H,S,D]
__device__ __nv_bfloat16 g_o[2ull*MM*EE];     // attention out hi/lo
__device__ float         g_x1[(size_t)MM*EE]; // x + proj (fp32)
__device__ __nv_bfloat16 g_h2[2ull*MM*EE];    // LN2 out hi/lo
__device__ __nv_bfloat16 g_mid[2ull*MM*FF];   // relu(ffn1) hi/lo
__device__ __nv_bfloat16 g_wqkv[2ull*1152*384];
__device__ __nv_bfloat16 g_wp[2ull*384*384];
__device__ __nv_bfloat16 g_w1[2ull*1536*384];
__device__ __nv_bfloat16 g_w2[2ull*384*1536];

// ---------------- helpers ---------------------------------------------------
__device__ __forceinline__ uint32_t smem_to_u32(const void* p) {
    uint32_t a;
    asm("{ .reg .u64 t; cvta.to.shared.u64 t, %1; cvt.u32.u64 %0, t; }"
        : "=r"(a) : "l"(p));
    return a;
}

#define CP_ASYNC16(sm, gp) \
    asm volatile("cp.async.cg.shared.global [%0], [%1], 16;" \
        :: "r"((uint32_t)(sm)), "l"(gp) : "memory")
#define CP_COMMIT() asm volatile("cp.async.commit_group;" ::: "memory")
#define CP_WAIT2()  asm volatile("cp.async.wait_group 2;" ::: "memory")

__device__ __forceinline__ void ldsm_x4(uint32_t* r, uint32_t addr) {
    asm volatile("ldmatrix.sync.aligned.m8n8.x4.shared.b16 {%0,%1,%2,%3}, [%4];"
        : "=r"(r[0]), "=r"(r[1]), "=r"(r[2]), "=r"(r[3]) : "r"(addr));
}
__device__ __forceinline__ void ldsm_x2(uint32_t* r, uint32_t addr) {
    asm volatile("ldmatrix.sync.aligned.m8n8.x2.shared.b16 {%0,%1}, [%2];"
        : "=r"(r[0]), "=r"(r[1]) : "r"(addr));
}
__device__ __forceinline__ void mma16816(float* d, const uint32_t* a, const uint32_t* b) {
    asm volatile(
        "mma.sync.aligned.m16n8k16.row.col.f32.bf16.bf16.f32 "
        "{%0,%1,%2,%3}, {%4,%5,%6,%7}, {%8,%9}, {%0,%1,%2,%3};"
        : "+f"(d[0]), "+f"(d[1]), "+f"(d[2]), "+f"(d[3])
        : "r"(a[0]), "r"(a[1]), "r"(a[2]), "r"(a[3]), "r"(b[0]), "r"(b[1]));
}

__device__ __forceinline__ void split_bf16(float v, __nv_bfloat16& hi, __nv_bfloat16& lo) {
    hi = __float2bfloat16(v);
    lo = __float2bfloat16(v - __bfloat162float(hi));
}

// ---------------- weight packing -------------------------------------------
__global__ void pack_qkv_kernel(const float* __restrict__ Wq,
                                const float* __restrict__ Wk,
                                const float* __restrict__ Wv) {
    int idx = blockIdx.x * 256 + threadIdx.x;
    if (idx >= 1152 * 384) return;
    int n = idx / 384, k = idx - n * 384;
    int m3 = n / 384;
    int rem = n - m3 * 384;
    int h = rem >> 6, d = rem & 63;
    const float* W = (m3 == 0) ? Wq : (m3 == 1) ? Wk : Wv;
    float v = W[((size_t)h * 384 + k) * 64 + d];
    __nv_bfloat16 hi, lo; split_bf16(v, hi, lo);
    g_wqkv[idx] = hi;
    g_wqkv[1152 * 384 + idx] = lo;
}

// B[n,k] = src[k*ldn + n], planes [2][N][K]
__global__ void pack_gen_kernel(const float* __restrict__ src, __nv_bfloat16* dst,
                                int N, int K, int ldn) {
    int idx = blockIdx.x * 256 + threadIdx.x;
    if (idx >= N * K) return;
    int n = idx / K, k = idx - n * K;
    float v = src[(size_t)k * ldn + n];
    __nv_bfloat16 hi, lo; split_bf16(v, hi, lo);
    dst[idx] = hi;
    dst[(size_t)N * K + idx] = lo;
}

// ---------------- LayerNorm -> hi/lo bf16 planes ---------------------------
__global__ void ln_kernel(const float* __restrict__ in,
                          const float* __restrict__ gamma,
                          const float* __restrict__ beta,
                          __nv_bfloat16* __restrict__ out) {
    __shared__ float red1[4];
    __shared__ float red2[4];
    int row = blockIdx.x;
    int tid = threadIdx.x;
    const float* r = in + (size_t)row * EE;
    float v0 = r[tid], v1 = r[tid + 128], v2 = r[tid + 256];
    float s = v0 + v1 + v2;
    #pragma unroll
    for (int o = 16; o; o >>= 1) s += __shfl_xor_sync(0xffffffffu, s, o);
    if ((tid & 31) == 0) red1[tid >> 5] = s;
    __syncthreads();
    float mu = (red1[0] + red1[1] + red1[2] + red1[3]) * (1.0f / 384.0f);
    float d0 = v0 - mu, d1 = v1 - mu, d2 = v2 - mu;
    float vs = d0 * d0 + d1 * d1 + d2 * d2;
    #pragma unroll
    for (int o = 16; o; o >>= 1) vs += __shfl_xor_sync(0xffffffffu, vs, o);
    if ((tid & 31) == 0) red2[tid >> 5] = vs;
    __syncthreads();
    float var = (red2[0] + red2[1] + red2[2] + red2[3]) * (1.0f / 384.0f);
    float rstd = rsqrtf(var + 1e-5f);
    __nv_bfloat16* hip = out + (size_t)row * EE;
    __nv_bfloat16* lop = hip + (size_t)MM * EE;
    #pragma unroll
    for (int j = 0; j < 3; j++) {
        int c = tid + j * 128;
        float d = (j == 0) ? d0 : (j == 1) ? d1 : d2;
        float y = d * rstd * gamma[c] + beta[c];
        __nv_bfloat16 hi, lo; split_bf16(y, hi, lo);
        hip[c] = hi;
        lop[c] = lo;
    }
}

// ---------------- mma.sync GEMM --------------------------------------------
// D[M,N] = sum over 3 segments: A_seg[M,K] . B_seg[N,K]^T  (bf16 hi/lo planes)
// seg 0: Ah.Bh   seg 1: Al.Bh   seg 2: Ah.Bl
// modes: 0 = QKV scatter fp32; 1 = resid + D + bias (fp32);
//        2 = relu(D+bias) -> hi/lo bf16; 3 = same as 1
// Tile: 128x128, BK=32, 4-stage cp.async pipeline, 8 warps, warp tile 64x32.
// Occupancy 2 CTA/SM (160KB smem of 228KB).
#define STAGE_BYTES 20480   // A: 128*80, B: 128*80
#define GSMEM (4 * STAGE_BYTES)

__global__ __launch_bounds__(256, 2)
void mma_gemm(const __nv_bfloat16* __restrict__ Ah, const __nv_bfloat16* __restrict__ Al,
              const __nv_bfloat16* __restrict__ Bh, const __nv_bfloat16* __restrict__ Bl,
              void* outp, const float* __restrict__ bias,
              const float* __restrict__ resid, int K, int N, int mode) {
    extern __shared__ __align__(128) uint8_t dsm[];
    const uint32_t sb = smem_to_u32(dsm);
    const int tid = threadIdx.x;
    const int lane = tid & 31;
    const int wid = tid >> 5;
    const int wm = wid >> 2;        // 0..1
    const int wn = wid & 3;         // 0..3
    const int m0 = blockIdx.y * 128;
    const int n0 = blockIdx.x * 128;
    const int kch = K >> 5;         // chunks per segment
    const int CT = 3 * kch;

    // per-thread load coordinates (2 chunks of 16B per matrix per stage)
    const int c0 = tid, c1 = tid + 256;
    const int r0 = c0 >> 2, q0 = c0 & 3;
    const int r1 = c1 >> 2, q1 = c1 & 3;

    float acc[4][4][4];
    #pragma unroll
    for (int i = 0; i < 4; i++)
        #pragma unroll
        for (int j = 0; j < 4; j++)
            #pragma unroll
            for (int t = 0; t < 4; t++) acc[i][j][t] = 0.0f;

    // ---- pipeline ----
    #define LOAD_STAGE(c) do { \
        int s_ = (c) & 3; \
        int seg_ = (c) / kch; \
        int kk_ = (c) - seg_ * kch; \
        const __nv_bfloat16* As_ = (seg_ == 1) ? Al : Ah; \
        const __nv_bfloat16* Bs_ = (seg_ == 2) ? Bl : Bh; \
        int k0_ = kk_ << 5; \
        uint32_t sa = sb + s_ * STAGE_BYTES; \
        uint32_t sbm = sa + 10240; \
        CP_ASYNC16(sa  + r0 * 80 + q0 * 16, As_ + (size_t)(m0 + r0) * K + k0_ + q0 * 8); \
        CP_ASYNC16(sa  + r1 * 80 + q1 * 16, As_ + (size_t)(m0 + r1) * K + k0_ + q1 * 8); \
        CP_ASYNC16(sbm + r0 * 80 + q0 * 16, Bs_ + (size_t)(n0 + r0) * K + k0_ + q0 * 8); \
        CP_ASYNC16(sbm + r1 * 80 + q1 * 16, Bs_ + (size_t)(n0 + r1) * K + k0_ + q1 * 8); \
    } while (0)

    LOAD_STAGE(0); CP_COMMIT();
    LOAD_STAGE(1); CP_COMMIT();
    LOAD_STAGE(2); CP_COMMIT();

    const uint32_t a_row = (uint32_t)(wm * 64 + (lane & 15));
    const uint32_t a_coff = (uint32_t)((lane >> 4) * 8) * 2;
    const uint32_t b_row = (uint32_t)(wn * 32 + (lane & 7));
    const uint32_t b_coff = (uint32_t)(((lane >> 3) & 1) * 8) * 2;

    for (int c = 0; c < CT; ++c) {
        CP_WAIT2();
        __syncthreads();   // all compute on stage c-1 done; stage c resident
        if (c + 3 < CT) { LOAD_STAGE(c + 3); }
        CP_COMMIT();
        uint32_t sa = sb + (c & 3) * STAGE_BYTES;
        uint32_t sbm = sa + 10240;
        #pragma unroll
        for (int ks = 0; ks < 2; ++ks) {
            uint32_t afr[4][4], bfr[4][2];
            #pragma unroll
            for (int mt = 0; mt < 4; ++mt)
                ldsm_x4(afr[mt], sa + (a_row + mt * 16) * 80 + ks * 32 + a_coff);
            #pragma unroll
            for (int nt = 0; nt < 4; ++nt)
                ldsm_x2(bfr[nt], sbm + (b_row + nt * 8) * 80 + ks * 32 + b_coff);
            #pragma unroll
            for (int mt = 0; mt < 4; ++mt)
                #pragma unroll
                for (int nt = 0; nt < 4; ++nt)
                    mma16816(acc[mt][nt], afr[mt], bfr[nt]);
        }
        // NOTE: no trailing barrier — next iteration's wait_group+barrier
        // orders buffer reuse (stage c+3 buffer == stage c-1 buffer).
    }

    // ---- epilogue: direct stores ----
    #pragma unroll
    for (int mt = 0; mt < 4; ++mt) {
        #pragma unroll
        for (int nt = 0; nt < 4; ++nt) {
            int col = n0 + wn * 32 + nt * 8 + (lane & 3) * 2;
            #pragma unroll
            for (int half = 0; half < 2; ++half) {
                int rg = m0 + wm * 64 + mt * 16 + (lane >> 2) + half * 8;
                float v0 = acc[mt][nt][half * 2 + 0];
                float v1 = acc[mt][nt][half * 2 + 1];
                if (mode == 0) {
                    int m3 = col / 384;
                    int rem = col - m3 * 384;
                    int h = rem >> 6, dd = rem & 63;
                    int b = rg >> 8, sq = rg & 255;
                    float2 val = make_float2(v0, v1);
                    *(float2*)((float*)outp + (size_t)m3 * BHSD +
                               ((size_t)((b * HH + h) * SS + sq)) * DH + dd) = val;
                } else if (mode == 2) {
                    float s0 = fmaxf(v0 + bias[col], 0.f);
                    float s1 = fmaxf(v1 + bias[col + 1], 0.f);
                    __nv_bfloat16 h0, l0, h1, l1;
                    split_bf16(s0, h0, l0); split_bf16(s1, h1, l1);
                    __nv_bfloat16* hip = (__nv_bfloat16*)outp;
                    __nv_bfloat16* lop = hip + (size_t)MM * FF;
                    size_t base = (size_t)rg * FF + col;
                    __nv_bfloat162 ph; ph.x = h0; ph.y = h1;
                    __nv_bfloat162 pl; pl.x = l0; pl.y = l1;
                    *(__nv_bfloat162*)(hip + base) = ph;
                    *(__nv_bfloat162*)(lop + base) = pl;
                } else {
                    float2 rr = *(const float2*)(resid + (size_t)rg * N + col);
                    float2 val = make_float2(v0 + bias[col] + rr.x,
                                             v1 + bias[col + 1] + rr.y);
                    *(float2*)((float*)outp + (size_t)rg * N + col) = val;
                }
            }
        }
    }
}

// ---------------- attention: online softmax, bf16 hi/lo output -------------
// SMSP-balanced query mapping: warp w handles query block (w<4 ? w : 11-w),
// so each SMSP's two warps sum to the same causal-loop length.
__global__ __launch_bounds__(256, 1)
void attn_kernel() {
    extern __shared__ float attnsm[];
    float* Ksm = attnsm;
    float* Vsm = attnsm + SS * DH;
    int bh = blockIdx.x;
    int b = bh / HH;
    int h = bh - b * HH;
    int tid = threadIdx.x;
    int lane = tid & 31;
    int wid = tid >> 5;

    const float* qb = g_qkv + (size_t)bh * SS * DH;
    const float* kb = g_qkv + BHSD + (size_t)bh * SS * DH;
    const float* vb = g_qkv + 2 * BHSD + (size_t)bh * SS * DH;

    const float4* k4 = (const float4*)kb;
    const float4* v4 = (const float4*)vb;
    float4* Ks4 = (float4*)Ksm;
    float4* Vs4 = (float4*)Vsm;
    #pragma unroll
    for (int i = 0; i < (SS * DH / 4) / 256; i++) {
        int idx = tid + i * 256;
        Ks4[idx] = k4[idx];
        Vs4[idx] = v4[idx];
    }
    __syncthreads();

    int qblk = (wid < 4) ? wid : 11 - wid;
    int s = qblk * 32 + lane;
    float4 q[16];
    const float4* qr = (const float4*)(qb + (size_t)s * DH);
    #pragma unroll
    for (int i = 0; i < 16; i++) q[i] = qr[i];

    const float scale = 0.125f;
    float mx = -1e30f, sum = 0.0f;
    float4 o[16];
    #pragma unroll
    for (int i = 0; i < 16; i++) o[i] = make_float4(0.f, 0.f, 0.f, 0.f);

    for (int t = 0; t <= s; t++) {
        const float4* kr = (const float4*)(Ksm + t * DH);
        float acc = 0.0f;
        #pragma unroll
        for (int i = 0; i < 16; i++) {
            float4 kk = kr[i];
            acc = fmaf(q[i].x, kk.x, acc);
            acc = fmaf(q[i].y, kk.y, acc);
            acc = fmaf(q[i].z, kk.z, acc);
            acc = fmaf(q[i].w, kk.w, acc);
        }
        float sc = acc * scale;
        float p;
        if (sc > mx) {
            float corr = __expf(mx - sc);
            sum *= corr;
            #pragma unroll
            for (int i = 0; i < 16; i++) {
                o[i].x *= corr; o[i].y *= corr; o[i].z *= corr; o[i].w *= corr;
            }
            mx = sc;
            p = 1.0f;
        } else {
            p = __expf(sc - mx);
        }
        sum += p;
        const float4* vr = (const float4*)(Vsm + t * DH);
        #pragma unroll
        for (int i = 0; i < 16; i++) {
            float4 vv = vr[i];
            o[i].x = fmaf(p, vv.x, o[i].x);
            o[i].y = fmaf(p, vv.y, o[i].y);
            o[i].z = fmaf(p, vv.z, o[i].z);
            o[i].w = fmaf(p, vv.w, o[i].w);
        }
    }
    float inv = 1.0f / sum;
    size_t off = (size_t)(b * SS + s) * EE + h * DH;
    __nv_bfloat16* hip = g_o + off;
    __nv_bfloat16* lop = g_o + (size_t)MM * EE + off;
    #pragma unroll
    for (int i = 0; i < 16; i++) {
        float f[4] = { o[i].x * inv, o[i].y * inv, o[i].z * inv, o[i].w * inv };
        __nv_bfloat162 ph, pl;
        __nv_bfloat16 hi, lo;
        split_bf16(f[0], hi, lo); ph.x = hi; pl.x = lo;
        split_bf16(f[1], hi, lo); ph.y = hi; pl.y = lo;
        *(__nv_bfloat162*)(hip + i * 4) = ph;
        *(__nv_bfloat162*)(lop + i * 4) = pl;
        split_bf16(f[2], hi, lo); ph.x = hi; pl.x = lo;
        split_bf16(f[3], hi, lo); ph.y = hi; pl.y = lo;
        *(__nv_bfloat162*)(hip + i * 4 + 2) = ph;
        *(__nv_bfloat162*)(lop + i * 4 + 2) = pl;
    }
}

// ---------------- host -----------------------------------------------------
extern "C" void kernel_launch(void* const* d_in, const int* in_sizes, int n_in,
                              void* d_out, int out_size) {
    const float* x   = (const float*)d_in[0];
    const float* Wq  = (const float*)d_in[1];
    const float* Wk  = (const float*)d_in[2];
    const float* Wv  = (const float*)d_in[3];
    const float* Wp  = (const float*)d_in[4];
    const float* bp  = (const float*)d_in[5];
    const float* W1  = (const float*)d_in[6];
    const float* b1  = (const float*)d_in[7];
    const float* W2  = (const float*)d_in[8];
    const float* b2  = (const float*)d_in[9];
    const float* g1  = (const float*)d_in[10];
    const float* be1 = (const float*)d_in[11];
    const float* g2  = (const float*)d_in[12];
    const float* be2 = (const float*)d_in[13];
    float* out = (float*)d_out;

    void *hlnv, *qkvv, *ov, *x1v, *h2v, *midv, *wqkvv, *wpv, *w1v, *w2v;
    cudaGetSymbolAddress(&hlnv,  g_hln);
    cudaGetSymbolAddress(&qkvv,  g_qkv);
    cudaGetSymbolAddress(&ov,    g_o);
    cudaGetSymbolAddress(&x1v,   g_x1);
    cudaGetSymbolAddress(&h2v,   g_h2);
    cudaGetSymbolAddress(&midv,  g_mid);
    cudaGetSymbolAddress(&wqkvv, g_wqkv);
    cudaGetSymbolAddress(&wpv,   g_wp);
    cudaGetSymbolAddress(&w1v,   g_w1);
    cudaGetSymbolAddress(&w2v,   g_w2);

    __nv_bfloat16* hln  = (__nv_bfloat16*)hlnv;
    float*         qkv  = (float*)qkvv;
    __nv_bfloat16* o    = (__nv_bfloat16*)ov;
    float*         x1   = (float*)x1v;
    __nv_bfloat16* h2   = (__nv_bfloat16*)h2v;
    __nv_bfloat16* mid  = (__nv_bfloat16*)midv;
    __nv_bfloat16* wqkv = (__nv_bfloat16*)wqkvv;
    __nv_bfloat16* wp   = (__nv_bfloat16*)wpv;
    __nv_bfloat16* w1   = (__nv_bfloat16*)w1v;
    __nv_bfloat16* w2   = (__nv_bfloat16*)w2v;

    cudaFuncSetAttribute(mma_gemm, cudaFuncAttributeMaxDynamicSharedMemorySize, GSMEM);
    cudaFuncSetAttribute(attn_kernel, cudaFuncAttributeMaxDynamicSharedMemorySize,
                         2 * SS * DH * (int)sizeof(float));

    // weight packing (hi/lo bf16)
    pack_qkv_kernel<<<(1152 * 384 + 255) / 256, 256>>>(Wq, Wk, Wv);
    pack_gen_kernel<<<(384 * 384 + 255) / 256, 256>>>(Wp, wp, 384, 384, 384);
    pack_gen_kernel<<<(1536 * 384 + 255) / 256, 256>>>(W1, w1, 1536, 384, 1536);
    pack_gen_kernel<<<(384 * 1536 + 255) / 256, 256>>>(W2, w2, 384, 1536, 384);
    // LN1
    ln_kernel<<<MM, 128>>>(x, g1, be1, hln);
    // QKV projection (scatter into [3][B,H,S,D] fp32)
    mma_gemm<<<dim3(9, 512), 256, GSMEM>>>(
        hln, hln + (size_t)MM * EE, wqkv, wqkv + (size_t)1152 * 384,
        qkv, nullptr, nullptr, 384, 1152, 0);
    // causal attention
    attn_kernel<<<BB * HH, 256, 2 * SS * DH * sizeof(float)>>>();
    // out projection + residual: x1 = x + o@Wp + bp
    mma_gemm<<<dim3(3, 512), 256, GSMEM>>>(
        o, o + (size_t)MM * EE, wp, wp + (size_t)384 * 384,
        x1, bp, x, 384, 384, 1);
    // LN2
    ln_kernel<<<MM, 128>>>(x1, g2, be2, h2);
    // FFN1 + relu -> hi/lo bf16
    mma_gemm<<<dim3(12, 512), 256, GSMEM>>>(
        h2, h2 + (size_t)MM * EE, w1, w1 + (size_t)1536 * 384,
        mid, b1, nullptr, 384, 1536, 2);
    // FFN2 + residual -> out
    mma_gemm<<<dim3(3, 512), 256, GSMEM>>>(
        mid, mid + (size_t)MM * FF, w2, w2 + (size_t)384 * 1536,
        out, b2, x1, 1536, 384, 3);
}

// round 9
// speedup vs baseline: 3.2935x; 1.8859x over previous
#include <cuda_runtime.h>
#include <cuda_bf16.h>
#include <cuda_fp16.h>
#include <cstdint>
#include <cstddef>

// ---------------- problem constants ----------------------------------------
#define BB 256
#define SS 256
#define EE 384
#define HH 6
#define DH 64
#define FF 1536
#define MM (BB*SS)                  // 65536
#define BHSD ((size_t)BB*HH*SS*DH)  // 25,165,824

// ---------------- scratch (device globals; no allocation allowed) ----------
__device__ __half  g_hln[(size_t)MM*EE];   // LN1 out fp16
__device__ __half  g_qkv[3*BHSD];          // q,k,v fp16 [3][B,H,S,D]
__device__ __half  g_o[(size_t)MM*EE];     // attention out fp16
__device__ float   g_x1[(size_t)MM*EE];    // x + proj (fp32)
__device__ __half  g_h2[(size_t)MM*EE];    // LN2 out fp16
__device__ __half  g_mid[(size_t)MM*FF];   // relu(ffn1) fp16
__device__ __half  g_wqkv[(size_t)1152*384];
__device__ __half  g_wp[(size_t)384*384];
__device__ __half  g_w1[(size_t)1536*384];
__device__ __half  g_w2[(size_t)384*1536];

// ---------------- helpers ---------------------------------------------------
__device__ __forceinline__ uint32_t smem_to_u32(const void* p) {
    uint32_t a;
    asm("{ .reg .u64 t; cvta.to.shared.u64 t, %1; cvt.u32.u64 %0, t; }"
        : "=r"(a) : "l"(p));
    return a;
}

#define CP_ASYNC16(sm, gp) \
    asm volatile("cp.async.cg.shared.global [%0], [%1], 16;" \
        :: "r"((uint32_t)(sm)), "l"(gp) : "memory")
#define CP_COMMIT() asm volatile("cp.async.commit_group;" ::: "memory")
#define CP_WAIT2()  asm volatile("cp.async.wait_group 2;" ::: "memory")

__device__ __forceinline__ void ldsm_x4(uint32_t* r, uint32_t addr) {
    asm volatile("ldmatrix.sync.aligned.m8n8.x4.shared.b16 {%0,%1,%2,%3}, [%4];"
        : "=r"(r[0]), "=r"(r[1]), "=r"(r[2]), "=r"(r[3]) : "r"(addr));
}
__device__ __forceinline__ void ldsm_x2(uint32_t* r, uint32_t addr) {
    asm volatile("ldmatrix.sync.aligned.m8n8.x2.shared.b16 {%0,%1}, [%2];"
        : "=r"(r[0]), "=r"(r[1]) : "r"(addr));
}
__device__ __forceinline__ void mma16816(float* d, const uint32_t* a, const uint32_t* b) {
    asm volatile(
        "mma.sync.aligned.m16n8k16.row.col.f32.f16.f16.f32 "
        "{%0,%1,%2,%3}, {%4,%5,%6,%7}, {%8,%9}, {%0,%1,%2,%3};"
        : "+f"(d[0]), "+f"(d[1]), "+f"(d[2]), "+f"(d[3])
        : "r"(a[0]), "r"(a[1]), "r"(a[2]), "r"(a[3]), "r"(b[0]), "r"(b[1]));
}

// ---------------- weight packing (fp16) -------------------------------------
__global__ void pack_qkv_kernel(const float* __restrict__ Wq,
                                const float* __restrict__ Wk,
                                const float* __restrict__ Wv) {
    int idx = blockIdx.x * 256 + threadIdx.x;
    if (idx >= 1152 * 384) return;
    int n = idx / 384, k = idx - n * 384;
    int m3 = n / 384;
    int rem = n - m3 * 384;
    int h = rem >> 6, d = rem & 63;
    const float* W = (m3 == 0) ? Wq : (m3 == 1) ? Wk : Wv;
    g_wqkv[idx] = __float2half(W[((size_t)h * 384 + k) * 64 + d]);
}

// B[n,k] = src[k*ldn + n]
__global__ void pack_gen_kernel(const float* __restrict__ src, __half* dst,
                                int N, int K, int ldn) {
    int idx = blockIdx.x * 256 + threadIdx.x;
    if (idx >= N * K) return;
    int n = idx / K, k = idx - n * K;
    dst[idx] = __float2half(src[(size_t)k * ldn + n]);
}

// ---------------- LayerNorm -> fp16 ----------------------------------------
__global__ void ln_kernel(const float* __restrict__ in,
                          const float* __restrict__ gamma,
                          const float* __restrict__ beta,
                          __half* __restrict__ out) {
    __shared__ float red1[4];
    __shared__ float red2[4];
    int row = blockIdx.x;
    int tid = threadIdx.x;
    const float* r = in + (size_t)row * EE;
    float v0 = r[tid], v1 = r[tid + 128], v2 = r[tid + 256];
    float s = v0 + v1 + v2;
    #pragma unroll
    for (int o = 16; o; o >>= 1) s += __shfl_xor_sync(0xffffffffu, s, o);
    if ((tid & 31) == 0) red1[tid >> 5] = s;
    __syncthreads();
    float mu = (red1[0] + red1[1] + red1[2] + red1[3]) * (1.0f / 384.0f);
    float d0 = v0 - mu, d1 = v1 - mu, d2 = v2 - mu;
    float vs = d0 * d0 + d1 * d1 + d2 * d2;
    #pragma unroll
    for (int o = 16; o; o >>= 1) vs += __shfl_xor_sync(0xffffffffu, vs, o);
    if ((tid & 31) == 0) red2[tid >> 5] = vs;
    __syncthreads();
    float var = (red2[0] + red2[1] + red2[2] + red2[3]) * (1.0f / 384.0f);
    float rstd = rsqrtf(var + 1e-5f);
    __half* w = out + (size_t)row * EE;
    #pragma unroll
    for (int j = 0; j < 3; j++) {
        int c = tid + j * 128;
        float d = (j == 0) ? d0 : (j == 1) ? d1 : d2;
        w[c] = __float2half(d * rstd * gamma[c] + beta[c]);
    }
}

// ---------------- mma.sync GEMM (fp16 in, fp32 accum) ----------------------
// D[M,N] = A[M,K] . B[N,K]^T
// modes: 0 = QKV scatter fp16; 1 = resid + D + bias (fp32);
//        2 = relu(D+bias) -> fp16; 3 = same as 1 (out to d_out)
// Tile: 128x128, BK=32, 4-stage cp.async pipeline, 8 warps, warp tile 64x32.
// Occupancy 2 CTA/SM (160KB smem of 228KB).
#define STAGE_BYTES 20480   // A: 128*80, B: 128*80
#define GSMEM (4 * STAGE_BYTES)

__global__ __launch_bounds__(256, 2)
void mma_gemm(const __half* __restrict__ A, const __half* __restrict__ B,
              void* outp, const float* __restrict__ bias,
              const float* __restrict__ resid, int K, int N, int mode) {
    extern __shared__ __align__(128) uint8_t dsm[];
    const uint32_t sb = smem_to_u32(dsm);
    const int tid = threadIdx.x;
    const int lane = tid & 31;
    const int wid = tid >> 5;
    const int wm = wid >> 2;        // 0..1
    const int wn = wid & 3;         // 0..3
    const int m0 = blockIdx.y * 128;
    const int n0 = blockIdx.x * 128;
    const int CT = K >> 5;          // K chunks of 32

    // per-thread load coordinates (2 chunks of 16B per matrix per stage)
    const int c0 = tid, c1 = tid + 256;
    const int r0 = c0 >> 2, q0 = c0 & 3;
    const int r1 = c1 >> 2, q1 = c1 & 3;

    float acc[4][4][4];
    #pragma unroll
    for (int i = 0; i < 4; i++)
        #pragma unroll
        for (int j = 0; j < 4; j++)
            #pragma unroll
            for (int t = 0; t < 4; t++) acc[i][j][t] = 0.0f;

    #define LOAD_STAGE(c) do { \
        int s_ = (c) & 3; \
        int k0_ = (c) << 5; \
        uint32_t sa = sb + s_ * STAGE_BYTES; \
        uint32_t sbm = sa + 10240; \
        CP_ASYNC16(sa  + r0 * 80 + q0 * 16, A + (size_t)(m0 + r0) * K + k0_ + q0 * 8); \
        CP_ASYNC16(sa  + r1 * 80 + q1 * 16, A + (size_t)(m0 + r1) * K + k0_ + q1 * 8); \
        CP_ASYNC16(sbm + r0 * 80 + q0 * 16, B + (size_t)(n0 + r0) * K + k0_ + q0 * 8); \
        CP_ASYNC16(sbm + r1 * 80 + q1 * 16, B + (size_t)(n0 + r1) * K + k0_ + q1 * 8); \
    } while (0)

    LOAD_STAGE(0); CP_COMMIT();
    LOAD_STAGE(1); CP_COMMIT();
    LOAD_STAGE(2); CP_COMMIT();

    const uint32_t a_row = (uint32_t)(wm * 64 + (lane & 15));
    const uint32_t a_coff = (uint32_t)((lane >> 4) * 8) * 2;
    const uint32_t b_row = (uint32_t)(wn * 32 + (lane & 7));
    const uint32_t b_coff = (uint32_t)(((lane >> 3) & 1) * 8) * 2;

    for (int c = 0; c < CT; ++c) {
        CP_WAIT2();
        __syncthreads();   // stage c resident; stage c-1 compute done
        if (c + 3 < CT) { LOAD_STAGE(c + 3); }
        CP_COMMIT();
        uint32_t sa = sb + (c & 3) * STAGE_BYTES;
        uint32_t sbm = sa + 10240;
        #pragma unroll
        for (int ks = 0; ks < 2; ++ks) {
            uint32_t afr[4][4], bfr[4][2];
            #pragma unroll
            for (int mt = 0; mt < 4; ++mt)
                ldsm_x4(afr[mt], sa + (a_row + mt * 16) * 80 + ks * 32 + a_coff);
            #pragma unroll
            for (int nt = 0; nt < 4; ++nt)
                ldsm_x2(bfr[nt], sbm + (b_row + nt * 8) * 80 + ks * 32 + b_coff);
            #pragma unroll
            for (int mt = 0; mt < 4; ++mt)
                #pragma unroll
                for (int nt = 0; nt < 4; ++nt)
                    mma16816(acc[mt][nt], afr[mt], bfr[nt]);
        }
        // no trailing barrier: next wait_group+barrier orders buffer reuse
    }

    // ---- epilogue: direct stores ----
    #pragma unroll
    for (int mt = 0; mt < 4; ++mt) {
        #pragma unroll
        for (int nt = 0; nt < 4; ++nt) {
            int col = n0 + wn * 32 + nt * 8 + (lane & 3) * 2;
            #pragma unroll
            for (int half_ = 0; half_ < 2; ++half_) {
                int rg = m0 + wm * 64 + mt * 16 + (lane >> 2) + half_ * 8;
                float v0 = acc[mt][nt][half_ * 2 + 0];
                float v1 = acc[mt][nt][half_ * 2 + 1];
                if (mode == 0) {
                    int m3 = col / 384;
                    int rem = col - m3 * 384;
                    int h = rem >> 6, dd = rem & 63;
                    int b = rg >> 8, sq = rg & 255;
                    __half2 val = __floats2half2_rn(v0, v1);
                    *(__half2*)((__half*)outp + (size_t)m3 * BHSD +
                                ((size_t)((b * HH + h) * SS + sq)) * DH + dd) = val;
                } else if (mode == 2) {
                    float s0 = fmaxf(v0 + bias[col], 0.f);
                    float s1 = fmaxf(v1 + bias[col + 1], 0.f);
                    *(__half2*)((__half*)outp + (size_t)rg * FF + col) =
                        __floats2half2_rn(s0, s1);
                } else {
                    float2 rr = *(const float2*)(resid + (size_t)rg * N + col);
                    float2 val = make_float2(v0 + bias[col] + rr.x,
                                             v1 + bias[col + 1] + rr.y);
                    *(float2*)((float*)outp + (size_t)rg * N + col) = val;
                }
            }
        }
    }
}

// ---------------- attention: online softmax, fp16 in/out, fp32 math --------
// SMSP-balanced query mapping: warp w -> query block (w<4 ? w : 11-w).
__global__ __launch_bounds__(256, 1)
void attn_kernel() {
    extern __shared__ float attnsm[];
    float* Ksm = attnsm;
    float* Vsm = attnsm + SS * DH;
    int bh = blockIdx.x;
    int b = bh / HH;
    int h = bh - b * HH;
    int tid = threadIdx.x;
    int lane = tid & 31;
    int wid = tid >> 5;

    const __half* qb = g_qkv + (size_t)bh * SS * DH;
    const __half* kb = g_qkv + BHSD + (size_t)bh * SS * DH;
    const __half* vb = g_qkv + 2 * BHSD + (size_t)bh * SS * DH;

    // load K,V (fp16 global) -> fp32 smem
    const uint4* k8 = (const uint4*)kb;   // 8 halves per uint4
    const uint4* v8 = (const uint4*)vb;
    #pragma unroll
    for (int i = 0; i < (SS * DH / 8) / 256; i++) {
        int idx = tid + i * 256;
        uint4 kk = k8[idx];
        uint4 vv = v8[idx];
        const __half2* kp = (const __half2*)&kk;
        const __half2* vp = (const __half2*)&vv;
        #pragma unroll
        for (int j = 0; j < 4; j++) {
            float2 kf = __half22float2(kp[j]);
            float2 vf = __half22float2(vp[j]);
            Ksm[idx * 8 + j * 2 + 0] = kf.x;
            Ksm[idx * 8 + j * 2 + 1] = kf.y;
            Vsm[idx * 8 + j * 2 + 0] = vf.x;
            Vsm[idx * 8 + j * 2 + 1] = vf.y;
        }
    }
    __syncthreads();

    int qblk = (wid < 4) ? wid : 11 - wid;
    int s = qblk * 32 + lane;
    float4 q[16];
    {
        const uint4* qr = (const uint4*)(qb + (size_t)s * DH);
        #pragma unroll
        for (int i = 0; i < 8; i++) {
            uint4 qq = qr[i];
            const __half2* qp = (const __half2*)&qq;
            float2 f0 = __half22float2(qp[0]);
            float2 f1 = __half22float2(qp[1]);
            float2 f2 = __half22float2(qp[2]);
            float2 f3 = __half22float2(qp[3]);
            q[i * 2 + 0] = make_float4(f0.x, f0.y, f1.x, f1.y);
            q[i * 2 + 1] = make_float4(f2.x, f2.y, f3.x, f3.y);
        }
    }

    const float scale = 0.125f;
    float mx = -1e30f, sum = 0.0f;
    float4 o[16];
    #pragma unroll
    for (int i = 0; i < 16; i++) o[i] = make_float4(0.f, 0.f, 0.f, 0.f);

    for (int t = 0; t <= s; t++) {
        const float4* kr = (const float4*)(Ksm + t * DH);
        float acc = 0.0f;
        #pragma unroll
        for (int i = 0; i < 16; i++) {
            float4 kk = kr[i];
            acc = fmaf(q[i].x, kk.x, acc);
            acc = fmaf(q[i].y, kk.y, acc);
            acc = fmaf(q[i].z, kk.z, acc);
            acc = fmaf(q[i].w, kk.w, acc);
        }
        float sc = acc * scale;
        float p;
        if (sc > mx) {
            float corr = __expf(mx - sc);
            sum *= corr;
            #pragma unroll
            for (int i = 0; i < 16; i++) {
                o[i].x *= corr; o[i].y *= corr; o[i].z *= corr; o[i].w *= corr;
            }
            mx = sc;
            p = 1.0f;
        } else {
            p = __expf(sc - mx);
        }
        sum += p;
        const float4* vr = (const float4*)(Vsm + t * DH);
        #pragma unroll
        for (int i = 0; i < 16; i++) {
            float4 vv = vr[i];
            o[i].x = fmaf(p, vv.x, o[i].x);
            o[i].y = fmaf(p, vv.y, o[i].y);
            o[i].z = fmaf(p, vv.z, o[i].z);
            o[i].w = fmaf(p, vv.w, o[i].w);
        }
    }
    float inv = 1.0f / sum;
    __half* ow = g_o + (size_t)(b * SS + s) * EE + h * DH;
    #pragma unroll
    for (int i = 0; i < 16; i++) {
        *(__half2*)(ow + i * 4 + 0) = __floats2half2_rn(o[i].x * inv, o[i].y * inv);
        *(__half2*)(ow + i * 4 + 2) = __floats2half2_rn(o[i].z * inv, o[i].w * inv);
    }
}

// ---------------- host -----------------------------------------------------
extern "C" void kernel_launch(void* const* d_in, const int* in_sizes, int n_in,
                              void* d_out, int out_size) {
    const float* x   = (const float*)d_in[0];
    const float* Wq  = (const float*)d_in[1];
    const float* Wk  = (const float*)d_in[2];
    const float* Wv  = (const float*)d_in[3];
    const float* Wp  = (const float*)d_in[4];
    const float* bp  = (const float*)d_in[5];
    const float* W1  = (const float*)d_in[6];
    const float* b1  = (const float*)d_in[7];
    const float* W2  = (const float*)d_in[8];
    const float* b2  = (const float*)d_in[9];
    const float* g1  = (const float*)d_in[10];
    const float* be1 = (const float*)d_in[11];
    const float* g2  = (const float*)d_in[12];
    const float* be2 = (const float*)d_in[13];
    float* out = (float*)d_out;

    void *hlnv, *qkvv, *ov, *x1v, *h2v, *midv, *wqkvv, *wpv, *w1v, *w2v;
    cudaGetSymbolAddress(&hlnv,  g_hln);
    cudaGetSymbolAddress(&qkvv,  g_qkv);
    cudaGetSymbolAddress(&ov,    g_o);
    cudaGetSymbolAddress(&x1v,   g_x1);
    cudaGetSymbolAddress(&h2v,   g_h2);
    cudaGetSymbolAddress(&midv,  g_mid);
    cudaGetSymbolAddress(&wqkvv, g_wqkv);
    cudaGetSymbolAddress(&wpv,   g_wp);
    cudaGetSymbolAddress(&w1v,   g_w1);
    cudaGetSymbolAddress(&w2v,   g_w2);

    __half* hln  = (__half*)hlnv;
    __half* qkv  = (__half*)qkvv;
    __half* o    = (__half*)ov;
    float*  x1   = (float*)x1v;
    __half* h2   = (__half*)h2v;
    __half* mid  = (__half*)midv;
    __half* wqkv = (__half*)wqkvv;
    __half* wp   = (__half*)wpv;
    __half* w1   = (__half*)w1v;
    __half* w2   = (__half*)w2v;

    cudaFuncSetAttribute(mma_gemm, cudaFuncAttributeMaxDynamicSharedMemorySize, GSMEM);
    cudaFuncSetAttribute(attn_kernel, cudaFuncAttributeMaxDynamicSharedMemorySize,
                         2 * SS * DH * (int)sizeof(float));

    // weight packing (fp16)
    pack_qkv_kernel<<<(1152 * 384 + 255) / 256, 256>>>(Wq, Wk, Wv);
    pack_gen_kernel<<<(384 * 384 + 255) / 256, 256>>>(Wp, wp, 384, 384, 384);
    pack_gen_kernel<<<(1536 * 384 + 255) / 256, 256>>>(W1, w1, 1536, 384, 1536);
    pack_gen_kernel<<<(384 * 1536 + 255) / 256, 256>>>(W2, w2, 384, 1536, 384);
    // LN1
    ln_kernel<<<MM, 128>>>(x, g1, be1, hln);
    // QKV projection (scatter into [3][B,H,S,D] fp16)
    mma_gemm<<<dim3(9, 512), 256, GSMEM>>>(
        hln, wqkv, qkv, nullptr, nullptr, 384, 1152, 0);
    // causal attention
    attn_kernel<<<BB * HH, 256, 2 * SS * DH * sizeof(float)>>>();
    // out projection + residual: x1 = x + o@Wp + bp
    mma_gemm<<<dim3(3, 512), 256, GSMEM>>>(
        o, wp, x1, bp, x, 384, 384, 1);
    // LN2
    ln_kernel<<<MM, 128>>>(x1, g2, be2, h2);
    // FFN1 + relu -> fp16
    mma_gemm<<<dim3(12, 512), 256, GSMEM>>>(
        h2, w1, mid, b1, nullptr, 384, 1536, 2);
    // FFN2 + residual -> out
    mma_gemm<<<dim3(3, 512), 256, GSMEM>>>(
        mid, w2, out, b2, x1, 1536, 384, 3);
}